// round 4
// baseline (speedup 1.0000x reference)
#include <cuda_runtime.h>
#include <math.h>

// Problem constants
#define B_  64
#define T_  512
#define H_  1024
#define I_  1024
#define M_TOK (B_ * T_)          // 32768 rows for the input projection

#define GRID_BLOCKS 128          // persistent kernel grid (must all be co-resident)
#define KSPLIT 16                // K chunks of 64
#define KCHUNK 64
#define NTILE  128               // cols per block tile
#define RTHREADS 512             // threads per persistent block

typedef unsigned long long u64t;

// ---------------------------------------------------------------------------
// Packed fp32x2 helpers (Blackwell FFMA2: 2 fp32 MACs per instruction)
// ---------------------------------------------------------------------------
__device__ __forceinline__ u64t ffma2(u64t a, u64t b, u64t c)
{
    u64t d;
    asm("fma.rn.f32x2 %0, %1, %2, %3;" : "=l"(d) : "l"(a), "l"(b), "l"(c));
    return d;
}
__device__ __forceinline__ u64t fadd2(u64t a, u64t b)
{
    u64t d;
    asm("add.rn.f32x2 %0, %1, %2;" : "=l"(d) : "l"(a), "l"(b));
    return d;
}
__device__ __forceinline__ u64t splat2(float x)
{
    u64t d;
    unsigned r = __float_as_uint(x);
    asm("mov.b64 %0, {%1, %2};" : "=l"(d) : "r"(r), "r"(r));
    return d;
}

// ---------------------------------------------------------------------------
// Scratch (no cudaMalloc allowed -> __device__ globals)
// ---------------------------------------------------------------------------
__device__ float g_xw[M_TOK * H_];              // input-projection result
__device__ float g_y0[M_TOK * H_];              // layer-0 output sequence
__device__ float g_h[B_ * H_];                  // hidden state
__device__ float g_partial[KSPLIT * B_ * H_];   // split-K partials (4 MB)

// flag-based grid barrier state (zero-initialized; reset at end of each launch)
__device__ unsigned g_flags[GRID_BLOCKS * 32];  // 128B stride per block
__device__ unsigned g_gen;

// Grid barrier, generation `gen` (monotonic within a launch, starting at 1).
// Arrival: each block releases its own flag. Block 0 gathers all flags with
// 128 threads, then releases g_gen. Everyone spins on g_gen.
__device__ __forceinline__ void grid_barrier(unsigned gen)
{
    __syncthreads();
    if (threadIdx.x == 0) {
        __threadfence();                                   // order prior stores
        volatile unsigned* mf = &g_flags[blockIdx.x * 32];
        *mf = gen;
    }
    if (blockIdx.x == 0) {
        if (threadIdx.x < GRID_BLOCKS) {
            volatile unsigned* f = &g_flags[threadIdx.x * 32];
            while (*f < gen) { }
        }
        __syncthreads();
        if (threadIdx.x == 0) {
            __threadfence();
            volatile unsigned* vg = &g_gen;
            *vg = gen;
        }
    }
    if (threadIdx.x == 0) {
        volatile unsigned* vg = &g_gen;
        while (*vg < gen) { }
        __threadfence();                                   // acquire
    }
    __syncthreads();
}

// ---------------------------------------------------------------------------
// Input-projection GEMM: C[m][n] = sum_k A[m][k] * W[n][k] + b1[n] + b2[n]
// 128x128 tile, BK=16, 256 threads, 8x8 per thread (packed fp32x2 over n).
// ---------------------------------------------------------------------------
__global__ __launch_bounds__(256) void gemm_bias_kernel(
    const float* __restrict__ A,
    const float* __restrict__ W,
    const float* __restrict__ b1,
    const float* __restrict__ b2,
    float* __restrict__ C,
    int M, int N, int K)
{
    __shared__ float As[16][128];
    __shared__ float Ws[16][128];

    const int m0 = blockIdx.y * 128;
    const int n0 = blockIdx.x * 128;
    const int tid = threadIdx.x;
    const int ty = tid >> 4;
    const int tx = tid & 15;

    const float* Ap = A + (size_t)m0 * K;
    const float* Wp = W + (size_t)n0 * K;

    const int f0  = tid;
    const int f1  = tid + 256;
    const int r0  = f0 >> 2, kq0 = (f0 & 3) * 4;
    const int r1  = f1 >> 2, kq1 = (f1 & 3) * 4;

    float4 pa0, pa1, pw0, pw1;
    pa0 = *(const float4*)(Ap + (size_t)r0 * K + kq0);
    pa1 = *(const float4*)(Ap + (size_t)r1 * K + kq1);
    pw0 = *(const float4*)(Wp + (size_t)r0 * K + kq0);
    pw1 = *(const float4*)(Wp + (size_t)r1 * K + kq1);

    u64t acc2[8][4];
#pragma unroll
    for (int i = 0; i < 8; i++)
#pragma unroll
        for (int j = 0; j < 4; j++) acc2[i][j] = 0ull;

    for (int k0 = 0; k0 < K; k0 += 16) {
        As[kq0 + 0][r0] = pa0.x; As[kq0 + 1][r0] = pa0.y;
        As[kq0 + 2][r0] = pa0.z; As[kq0 + 3][r0] = pa0.w;
        As[kq1 + 0][r1] = pa1.x; As[kq1 + 1][r1] = pa1.y;
        As[kq1 + 2][r1] = pa1.z; As[kq1 + 3][r1] = pa1.w;
        Ws[kq0 + 0][r0] = pw0.x; Ws[kq0 + 1][r0] = pw0.y;
        Ws[kq0 + 2][r0] = pw0.z; Ws[kq0 + 3][r0] = pw0.w;
        Ws[kq1 + 0][r1] = pw1.x; Ws[kq1 + 1][r1] = pw1.y;
        Ws[kq1 + 2][r1] = pw1.z; Ws[kq1 + 3][r1] = pw1.w;
        __syncthreads();

        if (k0 + 16 < K) {
            int kn = k0 + 16;
            pa0 = *(const float4*)(Ap + (size_t)r0 * K + kn + kq0);
            pa1 = *(const float4*)(Ap + (size_t)r1 * K + kn + kq1);
            pw0 = *(const float4*)(Wp + (size_t)r0 * K + kn + kq0);
            pw1 = *(const float4*)(Wp + (size_t)r1 * K + kn + kq1);
        }

#pragma unroll
        for (int kk = 0; kk < 16; kk++) {
            float a[8];
            *(float4*)(a)     = *(const float4*)&As[kk][ty * 8];
            *(float4*)(a + 4) = *(const float4*)&As[kk][ty * 8 + 4];
            ulonglong2 wA = *(const ulonglong2*)&Ws[kk][tx * 8];
            ulonglong2 wB = *(const ulonglong2*)&Ws[kk][tx * 8 + 4];
            u64t w2[4] = { wA.x, wA.y, wB.x, wB.y };
#pragma unroll
            for (int i = 0; i < 8; i++) {
                u64t ap = splat2(a[i]);
#pragma unroll
                for (int j = 0; j < 4; j++)
                    acc2[i][j] = ffma2(ap, w2[j], acc2[i][j]);
            }
        }
        __syncthreads();
    }

    u64t bv2[4];
#pragma unroll
    for (int j = 0; j < 4; j++) {
        int n = n0 + tx * 8 + j * 2;
        float blo = b1[n] + b2[n];
        float bhi = b1[n + 1] + b2[n + 1];
        unsigned lo = __float_as_uint(blo), hi = __float_as_uint(bhi);
        u64t p;
        asm("mov.b64 %0, {%1, %2};" : "=l"(p) : "r"(lo), "r"(hi));
        bv2[j] = p;
    }
#pragma unroll
    for (int i = 0; i < 8; i++) {
        int m = m0 + ty * 8 + i;
        float* cp = C + (size_t)m * N + n0 + tx * 8;
        ulonglong2 v0, v1;
        v0.x = fadd2(acc2[i][0], bv2[0]);
        v0.y = fadd2(acc2[i][1], bv2[1]);
        v1.x = fadd2(acc2[i][2], bv2[2]);
        v1.y = fadd2(acc2[i][3], bv2[3]);
        *(ulonglong2*)(cp)     = v0;
        *(ulonglong2*)(cp + 4) = v1;
    }
}

// ---------------------------------------------------------------------------
// Persistent recurrence kernel (one launch per layer).
// Grid: 128 blocks = 8 N-tiles (128 cols) x 16 K-chunks (64 k). 512 threads.
// Phase A: split-K partial GEMM (2b x 8c per thread); prefetches xw[t] at the
// top so the DRAM latency hides under compute. Phase B: reduce + tanh.
// ---------------------------------------------------------------------------
__global__ __launch_bounds__(RTHREADS) void rnn_layer_persistent(
    const float* __restrict__ Whh,    // [H, H]
    const float* __restrict__ xw,     // [B, T, H]
    float* __restrict__ y,            // [B, T, H]
    float* __restrict__ hlast)        // [B, H]
{
    __shared__ float Ws[KCHUNK][NTILE];   // 32 KB, W[c0+c][k0+k] -> Ws[k][c]
    __shared__ float Hs[KCHUNK][B_];      // 16 KB, h[b][k0+k]   -> Hs[k][b]

    const int tid = threadIdx.x;
    const int nt  = blockIdx.x >> 4;      // 0..7   N tile
    const int ks  = blockIdx.x & 15;      // 0..15  K chunk
    const int c0  = nt * NTILE;
    const int k0  = ks * KCHUNK;

    float* h       = g_h;
    float* partial = g_partial;

    // ---- load W chunk into smem once (persists across all steps) ----
    {
        int c   = tid & 127;
        int kb  = tid >> 7;               // 0..3
#pragma unroll
        for (int i = 0; i < 4; i++) {
            int kq = kb + 4 * i;          // 0..15
            float4 v = *(const float4*)(Whh + (size_t)(c0 + c) * H_ + k0 + kq * 4);
            Ws[kq * 4 + 0][c] = v.x;
            Ws[kq * 4 + 1][c] = v.y;
            Ws[kq * 4 + 2][c] = v.z;
            Ws[kq * 4 + 3][c] = v.w;
        }
    }

    // ---- zero h cooperatively (exactly B*H = 128*512 floats) ----
    h[blockIdx.x * RTHREADS + tid] = 0.0f;

    unsigned gen = 1;
    grid_barrier(gen++);

    const int tx = tid & 15;              // col group: 8 cols
    const int ty = tid >> 4;              // row group: 2 rows (0..31)

    // phase-B output index for this thread (1 output per thread)
    const int oidx = blockIdx.x * RTHREADS + tid;
    const int ob   = oidx >> 10;
    const int oc   = oidx & 1023;

    // Hs loader indices: 8 floats per thread
    const int lb = tid & 63;              // batch row
    const int lq = tid >> 6;              // 0..7 -> 8-float group within chunk

    for (int t = 0; t < T_; t++) {
        // prefetch xw for phase B (DRAM latency hides under phase A)
        float xv = __ldcg(xw + ((size_t)ob * T_ + t) * H_ + oc);

        // ---------- phase A: partial[ks][b][c] = sum_k h[b][k]*W[c][k] ----------
        {
            float4 v0 = __ldcg((const float4*)(h + (size_t)lb * H_ + k0 + lq * 8));
            float4 v1 = __ldcg((const float4*)(h + (size_t)lb * H_ + k0 + lq * 8 + 4));
            Hs[lq * 8 + 0][lb] = v0.x;
            Hs[lq * 8 + 1][lb] = v0.y;
            Hs[lq * 8 + 2][lb] = v0.z;
            Hs[lq * 8 + 3][lb] = v0.w;
            Hs[lq * 8 + 4][lb] = v1.x;
            Hs[lq * 8 + 5][lb] = v1.y;
            Hs[lq * 8 + 6][lb] = v1.z;
            Hs[lq * 8 + 7][lb] = v1.w;
        }
        __syncthreads();

        u64t acc2[2][4];
#pragma unroll
        for (int i = 0; i < 2; i++)
#pragma unroll
            for (int j = 0; j < 4; j++) acc2[i][j] = 0ull;

#pragma unroll 8
        for (int kk = 0; kk < KCHUNK; kk++) {
            float a[2];
            *(float2*)(a) = *(const float2*)&Hs[kk][ty * 2];
            ulonglong2 wA = *(const ulonglong2*)&Ws[kk][tx * 8];
            ulonglong2 wB = *(const ulonglong2*)&Ws[kk][tx * 8 + 4];
            u64t w2[4] = { wA.x, wA.y, wB.x, wB.y };
#pragma unroll
            for (int i = 0; i < 2; i++) {
                u64t ap = splat2(a[i]);
#pragma unroll
                for (int j = 0; j < 4; j++)
                    acc2[i][j] = ffma2(ap, w2[j], acc2[i][j]);
            }
        }

        // write partial tile (2 rows x 8 cols)
#pragma unroll
        for (int i = 0; i < 2; i++) {
            int m = ty * 2 + i;
            float* pp = partial + (size_t)ks * (B_ * H_) + (size_t)m * H_ + c0 + tx * 8;
            ulonglong2 v0, v1;
            v0.x = acc2[i][0]; v0.y = acc2[i][1];
            v1.x = acc2[i][2]; v1.y = acc2[i][3];
            *(ulonglong2*)(pp)     = v0;
            *(ulonglong2*)(pp + 4) = v1;
        }
        __syncthreads();          // protect Hs against next-step reload (cheap)

        grid_barrier(gen++);

        // ---------- phase B: reduce + tanh -> h, y ----------
        {
            float s = 0.0f;
#pragma unroll
            for (int k = 0; k < KSPLIT; k++)
                s += __ldcg(partial + (size_t)k * (B_ * H_) + oidx);
            float v = tanhf(s + xv);
            h[oidx] = v;
            y[((size_t)ob * T_ + t) * H_ + oc] = v;
            if (t == T_ - 1)
                hlast[oidx] = v;
        }

        grid_barrier(gen++);
    }

    // reset barrier state for next launch / graph replay (all blocks are past
    // their last barrier; block 0 finishing guarantees reset completes before
    // the kernel is observed as done)
    if (blockIdx.x == 0) {
        if (tid < GRID_BLOCKS) g_flags[tid * 32] = 0;
        __syncthreads();
        if (tid == 0) {
            __threadfence();
            g_gen = 0;
        }
    }
}

// ---------------------------------------------------------------------------
// Launcher: 4 graph nodes total.
// ---------------------------------------------------------------------------
extern "C" void kernel_launch(void* const* d_in, const int* in_sizes, int n_in,
                              void* d_out, int out_size)
{
    const float* X     = (const float*)d_in[0];
    const float* W_ih0 = (const float*)d_in[1];
    const float* b_ih0 = (const float*)d_in[2];
    const float* W_hh0 = (const float*)d_in[3];
    const float* b_hh0 = (const float*)d_in[4];
    const float* W_ih1 = (const float*)d_in[5];
    const float* b_ih1 = (const float*)d_in[6];
    const float* W_hh1 = (const float*)d_in[7];
    const float* b_hh1 = (const float*)d_in[8];

    float* out    = (float*)d_out;
    float* y_out  = out;                       // [B, T, H]
    float* h_last = out + (size_t)M_TOK * H_;  // [2, B, H]

    float* xw = nullptr;
    float* y0 = nullptr;
    cudaGetSymbolAddress((void**)&xw, g_xw);
    cudaGetSymbolAddress((void**)&y0, g_y0);

    dim3 ggrid(H_ / 128, M_TOK / 128);   // (8, 256)

    // ---------------- layer 0 ----------------
    gemm_bias_kernel<<<ggrid, 256>>>(X, W_ih0, b_ih0, b_hh0, xw, M_TOK, H_, I_);
    rnn_layer_persistent<<<GRID_BLOCKS, RTHREADS>>>(W_hh0, xw, y0, h_last);

    // ---------------- layer 1 ----------------
    gemm_bias_kernel<<<ggrid, 256>>>(y0, W_ih1, b_ih1, b_hh1, xw, M_TOK, H_, H_);
    rnn_layer_persistent<<<GRID_BLOCKS, RTHREADS>>>(W_hh1, xw, y_out, h_last + B_ * H_);
}

// round 5
// speedup vs baseline: 1.9021x; 1.9021x over previous
#include <cuda_runtime.h>
#include <math.h>

// Problem constants
#define B_  64
#define T_  512
#define H_  1024
#define I_  1024
#define M_TOK (B_ * T_)

#define NBLK 128            // persistent blocks (all co-resident, 1/SM)
#define NTHR 1024           // threads per persistent block

typedef unsigned long long u64t;

// ---------------------------------------------------------------------------
// Packed fp32x2 helpers (FFMA2: 2 fp32 MACs per instruction)
// ---------------------------------------------------------------------------
__device__ __forceinline__ u64t ffma2(u64t a, u64t b, u64t c)
{
    u64t d;
    asm("fma.rn.f32x2 %0, %1, %2, %3;" : "=l"(d) : "l"(a), "l"(b), "l"(c));
    return d;
}
__device__ __forceinline__ u64t fadd2(u64t a, u64t b)
{
    u64t d;
    asm("add.rn.f32x2 %0, %1, %2;" : "=l"(d) : "l"(a), "l"(b));
    return d;
}
__device__ __forceinline__ u64t splat2(float x)
{
    u64t d;
    unsigned r = __float_as_uint(x);
    asm("mov.b64 %0, {%1, %2};" : "=l"(d) : "r"(r), "r"(r));
    return d;
}
__device__ __forceinline__ u64t pack2(float lo, float hi)
{
    u64t d;
    unsigned a = __float_as_uint(lo), b = __float_as_uint(hi);
    asm("mov.b64 %0, {%1, %2};" : "=l"(d) : "r"(a), "r"(b));
    return d;
}
__device__ __forceinline__ float2 unpack2(u64t p)
{
    unsigned lo, hi;
    asm("mov.b64 {%0, %1}, %2;" : "=r"(lo), "=r"(hi) : "l"(p));
    return make_float2(__uint_as_float(lo), __uint_as_float(hi));
}

// ---------------------------------------------------------------------------
// Scratch (__device__ globals; no allocation allowed)
// ---------------------------------------------------------------------------
__device__ float g_xw[M_TOK * H_];       // input-projection result
__device__ float g_y0[M_TOK * H_];       // layer-0 output sequence
__device__ float g_hT[2][H_ * B_];       // ping-pong hidden state, TRANSPOSED h[k][b]
__device__ unsigned g_flags[NBLK * 32];  // barrier flags, 128B stride (zero-init)

// Distributed grid barrier: every block stores its flag, every block polls all
// flags. Two chained L2 latencies, no leader round-trip. Monotonic gens.
__device__ __forceinline__ void grid_barrier(unsigned gen)
{
    __syncthreads();
    if (threadIdx.x == 0) {
        __threadfence();                                  // release prior stores
        *(volatile unsigned*)&g_flags[blockIdx.x * 32] = gen;
    }
    if (threadIdx.x < NBLK) {
        volatile unsigned* f = &g_flags[threadIdx.x * 32];
        while ((int)(*f - gen) < 0) { }
        __threadfence();                                  // acquire
    }
    __syncthreads();
}

// ---------------------------------------------------------------------------
// Input-projection GEMM: C[m][n] = sum_k A[m][k]*W[n][k] + b1[n] + b2[n]
// 128x128 tile, BK=16, 256 threads, 8x8/thread, FFMA2-packed over n.
// ---------------------------------------------------------------------------
__global__ __launch_bounds__(256) void gemm_bias_kernel(
    const float* __restrict__ A,
    const float* __restrict__ W,
    const float* __restrict__ b1,
    const float* __restrict__ b2,
    float* __restrict__ C,
    int M, int N, int K)
{
    __shared__ float As[16][128];
    __shared__ float Ws[16][128];

    const int m0 = blockIdx.y * 128;
    const int n0 = blockIdx.x * 128;
    const int tid = threadIdx.x;
    const int ty = tid >> 4;
    const int tx = tid & 15;

    const float* Ap = A + (size_t)m0 * K;
    const float* Wp = W + (size_t)n0 * K;

    const int f0  = tid;
    const int f1  = tid + 256;
    const int r0  = f0 >> 2, kq0 = (f0 & 3) * 4;
    const int r1  = f1 >> 2, kq1 = (f1 & 3) * 4;

    float4 pa0 = *(const float4*)(Ap + (size_t)r0 * K + kq0);
    float4 pa1 = *(const float4*)(Ap + (size_t)r1 * K + kq1);
    float4 pw0 = *(const float4*)(Wp + (size_t)r0 * K + kq0);
    float4 pw1 = *(const float4*)(Wp + (size_t)r1 * K + kq1);

    u64t acc2[8][4];
#pragma unroll
    for (int i = 0; i < 8; i++)
#pragma unroll
        for (int j = 0; j < 4; j++) acc2[i][j] = 0ull;

    for (int k0 = 0; k0 < K; k0 += 16) {
        As[kq0 + 0][r0] = pa0.x; As[kq0 + 1][r0] = pa0.y;
        As[kq0 + 2][r0] = pa0.z; As[kq0 + 3][r0] = pa0.w;
        As[kq1 + 0][r1] = pa1.x; As[kq1 + 1][r1] = pa1.y;
        As[kq1 + 2][r1] = pa1.z; As[kq1 + 3][r1] = pa1.w;
        Ws[kq0 + 0][r0] = pw0.x; Ws[kq0 + 1][r0] = pw0.y;
        Ws[kq0 + 2][r0] = pw0.z; Ws[kq0 + 3][r0] = pw0.w;
        Ws[kq1 + 0][r1] = pw1.x; Ws[kq1 + 1][r1] = pw1.y;
        Ws[kq1 + 2][r1] = pw1.z; Ws[kq1 + 3][r1] = pw1.w;
        __syncthreads();

        if (k0 + 16 < K) {
            int kn = k0 + 16;
            pa0 = *(const float4*)(Ap + (size_t)r0 * K + kn + kq0);
            pa1 = *(const float4*)(Ap + (size_t)r1 * K + kn + kq1);
            pw0 = *(const float4*)(Wp + (size_t)r0 * K + kn + kq0);
            pw1 = *(const float4*)(Wp + (size_t)r1 * K + kn + kq1);
        }

#pragma unroll
        for (int kk = 0; kk < 16; kk++) {
            float a[8];
            *(float4*)(a)     = *(const float4*)&As[kk][ty * 8];
            *(float4*)(a + 4) = *(const float4*)&As[kk][ty * 8 + 4];
            ulonglong2 wA = *(const ulonglong2*)&Ws[kk][tx * 8];
            ulonglong2 wB = *(const ulonglong2*)&Ws[kk][tx * 8 + 4];
            u64t w2[4] = { wA.x, wA.y, wB.x, wB.y };
#pragma unroll
            for (int i = 0; i < 8; i++) {
                u64t ap = splat2(a[i]);
#pragma unroll
                for (int j = 0; j < 4; j++)
                    acc2[i][j] = ffma2(ap, w2[j], acc2[i][j]);
            }
        }
        __syncthreads();
    }

    u64t bv2[4];
#pragma unroll
    for (int j = 0; j < 4; j++) {
        int n = n0 + tx * 8 + j * 2;
        bv2[j] = pack2(b1[n] + b2[n], b1[n + 1] + b2[n + 1]);
    }
#pragma unroll
    for (int i = 0; i < 8; i++) {
        int m = m0 + ty * 8 + i;
        float* cp = C + (size_t)m * N + n0 + tx * 8;
        ulonglong2 v0, v1;
        v0.x = fadd2(acc2[i][0], bv2[0]);
        v0.y = fadd2(acc2[i][1], bv2[1]);
        v1.x = fadd2(acc2[i][2], bv2[2]);
        v1.y = fadd2(acc2[i][3], bv2[3]);
        *(ulonglong2*)(cp)     = v0;
        *(ulonglong2*)(cp + 4) = v1;
    }
}

// ---------------------------------------------------------------------------
// Persistent recurrence kernel: one launch per layer, ONE grid barrier/step.
// 128 blocks x 1024 threads. Block owns 8 output columns (c0..c0+7), full K.
//   warp w (0..31) = k-slice [w*32, w*32+32)
//   lane l (0..31) = batch rows {2l, 2l+1}, all 8 cols (4 f32x2 col-pairs)
// W_hh col-pairs packed in smem; per k-iter all lanes read the same 32B
// (broadcast). h stored transposed h[k][b] (ping-pong) -> 256B/warp-iter
// contiguous L2 reads. Block-local smem reduction over the 32 k-slices.
// ---------------------------------------------------------------------------
#define RS_STRIDE 33   // u64 stride for reduction rows (bank-conflict pad)

__global__ __launch_bounds__(NTHR, 1) void rnn_layer_persistent(
    const float* __restrict__ Whh,    // [H, H]
    const float* __restrict__ xw,     // [B, T, H]
    float* __restrict__ y,            // [B, T, H]
    float* __restrict__ hlast)        // [B, H]
{
    extern __shared__ char smem[];
    u64t* Wsm = (u64t*)smem;                        // [H_*4] : Wsm[k*4+cp] = (W[c0+2cp][k], W[c0+2cp+1][k])
    u64t* Rs  = (u64t*)(smem + H_ * 4 * 8);         // [256 * RS_STRIDE]

    const int tid = threadIdx.x;
    const int w   = tid >> 5;        // k-slice
    const int l   = tid & 31;        // b-group (2 rows)
    const int c0  = blockIdx.x * 8;

    // ---- pack W columns into smem once per layer ----
    for (int idx = tid; idx < H_ * 4; idx += NTHR) {
        int k  = idx >> 2;
        int cp = idx & 3;
        float lo = Whh[(size_t)(c0 + 2 * cp)     * H_ + k];
        float hi = Whh[(size_t)(c0 + 2 * cp + 1) * H_ + k];
        Wsm[idx] = pack2(lo, hi);
    }

    // ---- zero initial hidden state (buffer 0) ----
    {
        int g = blockIdx.x * NTHR + tid;
        if (g < H_ * B_) g_hT[0][g] = 0.0f;
    }

    // ---- monotonic barrier generations, seeded from this block's own flag ----
    unsigned gen = g_flags[blockIdx.x * 32] + 1;
    grid_barrier(gen++);

    // finalize-thread mapping (threads 0..255): fb = batch row, fcp = col pair
    const int fb  = tid & 63;
    const int fcp = tid >> 6;        // valid when tid < 256

    const int kbase = w * 32;

    for (int t = 0; t < T_; t++) {
        const float2* hin = (const float2*)g_hT[t & 1];        // [k][b] as float2 pairs
        float*        hout = g_hT[(t + 1) & 1];

        // prefetch xw for finalize (hides DRAM latency under main loop)
        u64t xv = 0ull;
        if (tid < 256)
            xv = *(const u64t*)&xw[((size_t)fb * T_ + t) * H_ + c0 + fcp * 2];

        // ---- main loop: full-K partial for this warp's k-slice ----
        u64t acc00 = 0, acc01 = 0, acc02 = 0, acc03 = 0;   // b = 2l
        u64t acc10 = 0, acc11 = 0, acc12 = 0, acc13 = 0;   // b = 2l+1
#pragma unroll 8
        for (int i = 0; i < 32; i++) {
            int k = kbase + i;
            float2 h2 = __ldcg(&hin[k * 32 + l]);          // h[k][2l], h[k][2l+1]
            ulonglong2 wv0 = *(const ulonglong2*)&Wsm[k * 4];       // cp 0,1 (broadcast)
            ulonglong2 wv1 = *(const ulonglong2*)&Wsm[k * 4 + 2];   // cp 2,3 (broadcast)
            u64t a0 = splat2(h2.x);
            u64t a1 = splat2(h2.y);
            acc00 = ffma2(a0, wv0.x, acc00);
            acc01 = ffma2(a0, wv0.y, acc01);
            acc02 = ffma2(a0, wv1.x, acc02);
            acc03 = ffma2(a0, wv1.y, acc03);
            acc10 = ffma2(a1, wv0.x, acc10);
            acc11 = ffma2(a1, wv0.y, acc11);
            acc12 = ffma2(a1, wv1.x, acc12);
            acc13 = ffma2(a1, wv1.y, acc13);
        }

        // ---- block-local k-slice reduction via smem ----
        // output row o = cp*64 + b  (b = 2l or 2l+1), column = warp w
        {
            int b0 = 2 * l, b1 = 2 * l + 1;
            Rs[(0 * 64 + b0) * RS_STRIDE + w] = acc00;
            Rs[(1 * 64 + b0) * RS_STRIDE + w] = acc01;
            Rs[(2 * 64 + b0) * RS_STRIDE + w] = acc02;
            Rs[(3 * 64 + b0) * RS_STRIDE + w] = acc03;
            Rs[(0 * 64 + b1) * RS_STRIDE + w] = acc10;
            Rs[(1 * 64 + b1) * RS_STRIDE + w] = acc11;
            Rs[(2 * 64 + b1) * RS_STRIDE + w] = acc12;
            Rs[(3 * 64 + b1) * RS_STRIDE + w] = acc13;
        }
        __syncthreads();

        // ---- finalize: threads 0..255, one col-pair x one batch row each ----
        if (tid < 256) {
            const u64t* row = &Rs[tid * RS_STRIDE];
            u64t s = fadd2(row[0], row[1]);
            u64t s2 = fadd2(row[2], row[3]);
#pragma unroll
            for (int ks = 4; ks < 32; ks += 4) {
                s  = fadd2(s,  fadd2(row[ks],     row[ks + 1]));
                s2 = fadd2(s2, fadd2(row[ks + 2], row[ks + 3]));
            }
            s = fadd2(fadd2(s, s2), xv);
            float2 sv = unpack2(s);
            float v0 = tanhf(sv.x);
            float v1 = tanhf(sv.y);
            int cA = c0 + fcp * 2;
            // transposed hidden state for next step (coalesced over fb)
            hout[(cA)     * 64 + fb] = v0;
            hout[(cA + 1) * 64 + fb] = v1;
            // sequence output y[b][t][c]
            *(u64t*)&y[((size_t)fb * T_ + t) * H_ + cA] = pack2(v0, v1);
            if (t == T_ - 1)
                *(u64t*)&hlast[(size_t)fb * H_ + cA] = pack2(v0, v1);
        }

        grid_barrier(gen++);
    }
}

// ---------------------------------------------------------------------------
// Launcher: 4 graph nodes.
// ---------------------------------------------------------------------------
extern "C" void kernel_launch(void* const* d_in, const int* in_sizes, int n_in,
                              void* d_out, int out_size)
{
    const float* X     = (const float*)d_in[0];
    const float* W_ih0 = (const float*)d_in[1];
    const float* b_ih0 = (const float*)d_in[2];
    const float* W_hh0 = (const float*)d_in[3];
    const float* b_hh0 = (const float*)d_in[4];
    const float* W_ih1 = (const float*)d_in[5];
    const float* b_ih1 = (const float*)d_in[6];
    const float* W_hh1 = (const float*)d_in[7];
    const float* b_hh1 = (const float*)d_in[8];

    float* out    = (float*)d_out;
    float* y_out  = out;                       // [B, T, H]
    float* h_last = out + (size_t)M_TOK * H_;  // [2, B, H]

    float* xw = nullptr;
    float* y0 = nullptr;
    cudaGetSymbolAddress((void**)&xw, g_xw);
    cudaGetSymbolAddress((void**)&y0, g_y0);

    const int rnn_smem = H_ * 4 * 8 + 256 * RS_STRIDE * 8;   // 32KB + 67.6KB
    static int attr_set = 0;
    if (!attr_set) {
        cudaFuncSetAttribute(rnn_layer_persistent,
                             cudaFuncAttributeMaxDynamicSharedMemorySize, rnn_smem);
        attr_set = 1;
    }

    dim3 ggrid(H_ / 128, M_TOK / 128);   // (8, 256)

    // ---------------- layer 0 ----------------
    gemm_bias_kernel<<<ggrid, 256>>>(X, W_ih0, b_ih0, b_hh0, xw, M_TOK, H_, I_);
    rnn_layer_persistent<<<NBLK, NTHR, rnn_smem>>>(W_hh0, xw, y0, h_last);

    // ---------------- layer 1 ----------------
    gemm_bias_kernel<<<ggrid, 256>>>(y0, W_ih1, b_ih1, b_hh1, xw, M_TOK, H_, H_);
    rnn_layer_persistent<<<NBLK, NTHR, rnn_smem>>>(W_hh1, xw, y_out, h_last + B_ * H_);
}